// round 3
// baseline (speedup 1.0000x reference)
#include <cuda_runtime.h>
#include <math.h>

#define HW   1024
#define DM   64
#define DS   16
#define NV   25
#define TIN  4

// ---------------- scratch (static device globals; no allocation) ----------------
__device__ float g_state[(size_t)NV * DS * HW * DM];   // drifting-frame state [v][n][q][d], ~105 MB
__device__ float g_u[TIN * HW * DM];
__device__ float g_e1[TIN * HW * DM];
__device__ float g_cc[TIN * HW * 96];                  // [t][px][dconv|B|C]
__device__ float g_wpack[96 * 576];                    // wd|wB|wC transposed to [oc][tap][ic]
__device__ float g_wenc2[64 * 576];                    // enc_w2 transposed
__device__ float g_wdec1[64 * 576];
__device__ float g_wdec2[64 * 576];
__device__ float g_bpack[96];
__device__ float g_A[DS * DM];                         // A[n][d] = -exp(logA[d][n])
__device__ float g_rA[DS * DM];
__device__ int   g_uniA;
__device__ float g_ymax[HW * DM];
__device__ float g_d1[HW * DM];
__device__ float g_d2[HW * DM];

// ---------------- pack: weight transposes + bias + A fields (one launch) ----------------
__global__ void pack_all(const float* __restrict__ wd, const float* __restrict__ bd,
                         const float* __restrict__ wB, const float* __restrict__ wC,
                         const float* __restrict__ logA,
                         const float* __restrict__ ew2, const float* __restrict__ dw1,
                         const float* __restrict__ dw2)
{
    int k = blockIdx.x * 256 + threadIdx.x;
    const int R0 = 96 * 576;           // wpack
    const int R1 = R0 + 3 * 64 * 576;  // enc2/dec1/dec2
    if (k < R0) {
        int oc = k / 576, rem = k - oc * 576;
        int tap = rem >> 6, ic = rem & 63;
        float v;
        if (oc < 64)      v = wd[oc * 576 + ic * 9 + tap];
        else if (oc < 80) v = wB[(oc - 64) * 576 + ic * 9 + tap];
        else              v = wC[(oc - 80) * 576 + ic * 9 + tap];
        g_wpack[k] = v;
    } else if (k < R1) {
        int k2 = k - R0;
        int which = k2 / (64 * 576);
        int k3 = k2 - which * (64 * 576);
        int oc = k3 / 576, rem = k3 - oc * 576;
        int tap = rem >> 6, ic = rem & 63;
        const float* s = (which == 0) ? ew2 : ((which == 1) ? dw1 : dw2);
        float v = s[oc * 576 + ic * 9 + tap];
        if (which == 0) g_wenc2[k3] = v;
        else if (which == 1) g_wdec1[k3] = v;
        else g_wdec2[k3] = v;
    }
    if (k < DM)       g_bpack[k] = bd[k];
    else if (k < 96)  g_bpack[k] = 0.f;
    if (k < DS * DM) {
        int n = k >> 6, d = k & 63;
        float a = -expf(logA[d * DS + n]);
        g_A[k] = a;
        g_rA[k] = 1.f / a;
    }
}

// uniform-A detection (generic fallback stays correct for any input)
__global__ void check_uni(const float* __restrict__ logA)
{
    __shared__ int ok;
    if (threadIdx.x == 0) ok = 1;
    __syncthreads();
    float a0 = logA[0];
    for (int i = threadIdx.x; i < DM * DS; i += 256)
        if (logA[i] != a0) atomicAnd(&ok, 0);
    __syncthreads();
    if (threadIdx.x == 0) g_uniA = ok;
}

// ---------------- channel-last circular 3x3 conv, IC=64, 4 oc/thread ----------------
// x: [z][px][64]; wgt pre-transposed [oc][tap][ic]; y: [z][px][OC].
// Block = 64 threads = 32 px (1 row) x 2 oc-quads (8 oc/block). grid=(32, OC/8, z).
// Inner step: 1 lane-distinct x LDS.128 + 4 warp-broadcast w LDS.128 -> 16 FMA.
template <bool RELU>
__global__ __launch_bounds__(64) void conv8(const float* __restrict__ x,
                                            const float* __restrict__ wgt,
                                            const float* __restrict__ bias,
                                            float* __restrict__ y, int OC)
{
    __shared__ float4 xs[3 * 32 * 17];    // 26 KB, 17-pad -> conflict-free LDS.128
    __shared__ float  ws[8 * 576];        // 18 KB, [ocl][tap][ic]
    __shared__ float  bs[8];
    const int tid = threadIdx.x;
    const int obase = blockIdx.y * 8;
    const int r0 = blockIdx.x;
    x += (size_t)blockIdx.z * DM * HW;
    y += (size_t)blockIdx.z * (size_t)OC * HW;

    // stage x rows r0-1..r0+1 (coalesced float4)
    const float4* x4 = (const float4*)x;
    for (int k = tid; k < 3 * 32 * 16; k += 64) {
        int lr = k >> 9; int rem = k & 511; int c = rem >> 4; int icv = rem & 15;
        int row = (r0 - 1 + lr) & 31;
        xs[(lr * 32 + c) * 17 + icv] = x4[(((row << 5) + c) << 4) + icv];
    }
    // stage 8 oc of pre-transposed weights: direct coalesced float4 copy
    {
        const float4* wsrc = (const float4*)(wgt + obase * 576);
        float4* wdst = (float4*)ws;
        for (int k = tid; k < 8 * 144; k += 64) wdst[k] = wsrc[k];
    }
    if (tid < 8) bs[tid] = bias[obase + tid];
    __syncthreads();

    const int q = tid >> 5;               // oc-quad (warp-uniform)
    const int c = tid & 31;
    const int cm = (c + 31) & 31, cp = (c + 1) & 31;
    int cxs[3]; cxs[0] = cm; cxs[1] = c; cxs[2] = cp;

    float a0 = bs[q * 4 + 0], a1 = bs[q * 4 + 1], a2 = bs[q * 4 + 2], a3 = bs[q * 4 + 3];
    const float4* w0 = (const float4*)&ws[(q * 4 + 0) * 576];
    const float4* w1 = (const float4*)&ws[(q * 4 + 1) * 576];
    const float4* w2 = (const float4*)&ws[(q * 4 + 2) * 576];
    const float4* w3 = (const float4*)&ws[(q * 4 + 3) * 576];

#pragma unroll 1
    for (int tap = 0; tap < 9; tap++) {
        int tr = tap / 3;
        int tc = tap - tr * 3;
        const float4* xp = &xs[(tr * 32 + cxs[tc]) * 17];
        const int toff = tap * 16;
#pragma unroll
        for (int icv = 0; icv < 16; icv++) {
            float4 xv = xp[icv];
            float4 v0 = w0[toff + icv];
            float4 v1 = w1[toff + icv];
            float4 v2 = w2[toff + icv];
            float4 v3 = w3[toff + icv];
            a0 = fmaf(xv.x, v0.x, fmaf(xv.y, v0.y, fmaf(xv.z, v0.z, fmaf(xv.w, v0.w, a0))));
            a1 = fmaf(xv.x, v1.x, fmaf(xv.y, v1.y, fmaf(xv.z, v1.z, fmaf(xv.w, v1.w, a1))));
            a2 = fmaf(xv.x, v2.x, fmaf(xv.y, v2.y, fmaf(xv.z, v2.z, fmaf(xv.w, v2.w, a2))));
            a3 = fmaf(xv.x, v3.x, fmaf(xv.y, v3.y, fmaf(xv.z, v3.z, fmaf(xv.w, v3.w, a3))));
        }
    }
    if (RELU) {
        a0 = fmaxf(a0, 0.f); a1 = fmaxf(a1, 0.f);
        a2 = fmaxf(a2, 0.f); a3 = fmaxf(a3, 0.f);
    }
    const int px = (r0 << 5) + c;
    float4 o; o.x = a0; o.y = a1; o.z = a2; o.w = a3;
    *(float4*)&y[(size_t)px * OC + obase + q * 4] = o;
}

// ---------------- channel-last conv, IC=1 (encoder stage 1) ----------------
__global__ __launch_bounds__(128) void conv1_cl(const float* __restrict__ x,
                                                const float* __restrict__ wgt,
                                                const float* __restrict__ bias,
                                                float* __restrict__ y)
{
    __shared__ float xs[6 * 32];
    __shared__ float ws[4][9];
    __shared__ float bs[4];
    const int tid = threadIdx.x;
    const int obase = blockIdx.y * 4;
    x += blockIdx.z * HW;
    y += (size_t)blockIdx.z * DM * HW;
    const int r0 = blockIdx.x * 4;
    for (int k = tid; k < 6 * 32; k += 128) {
        int lr = k >> 5, c = k & 31;
        xs[k] = x[(((r0 - 1 + lr) & 31) << 5) + c];
    }
    if (tid < 36) ws[tid / 9][tid % 9] = wgt[(obase + tid / 9) * 9 + tid % 9];
    if (tid < 4)  bs[tid] = bias[obase + tid];
    __syncthreads();

    const int hl = tid >> 5, c = tid & 31;
    const int cm = (c + 31) & 31, cp = (c + 1) & 31;
    float xv[9];
#pragma unroll
    for (int tr = 0; tr < 3; tr++) {
        xv[tr * 3 + 0] = xs[(hl + tr) * 32 + cm];
        xv[tr * 3 + 1] = xs[(hl + tr) * 32 + c];
        xv[tr * 3 + 2] = xs[(hl + tr) * 32 + cp];
    }
    float4 o; float* op = &o.x;
#pragma unroll
    for (int j = 0; j < 4; j++) {
        float a = bs[j];
#pragma unroll
        for (int t9 = 0; t9 < 9; t9++) a = fmaf(xv[t9], ws[j][t9], a);
        op[j] = fmaxf(a, 0.f);
    }
    const int px = blockIdx.x * 128 + tid;
    *(float4*)&y[(size_t)px * DM + obase] = o;
}

// ---------------- channel-last conv, OC=1 (decoder out) ----------------
__global__ __launch_bounds__(128) void conv_out(const float* __restrict__ x,
                                                const float* __restrict__ wgt,
                                                const float* __restrict__ bias,
                                                float* __restrict__ y)
{
    __shared__ float4 xs[3 * 32 * 17];
    __shared__ float  ws[9][64];
    const int tid = threadIdx.x;
    const int r0 = blockIdx.x;
    const float4* x4 = (const float4*)x;
    for (int k = tid; k < 3 * 32 * 16; k += 128) {
        int lr = k >> 9; int rem = k & 511; int c = rem >> 4; int icv = rem & 15;
        int row = (r0 - 1 + lr) & 31;
        xs[(lr * 32 + c) * 17 + icv] = x4[(((row << 5) + c) << 4) + icv];
    }
    for (int k = tid; k < 576; k += 128) {
        int tap = k >> 6, ic = k & 63;
        ws[tap][ic] = wgt[ic * 9 + tap];
    }
    __syncthreads();

    const int icq = tid & 3, c = tid >> 2;
    const int cm = (c + 31) & 31, cp = (c + 1) & 31;
    float acc = 0.f;
#pragma unroll
    for (int tr = 0; tr < 3; tr++) {
#pragma unroll
        for (int tc = 0; tc < 3; tc++) {
            const int cx = (tc == 0) ? cm : ((tc == 1) ? c : cp);
            const float4* xp = &xs[(tr * 32 + cx) * 17];
            const float4* wp = (const float4*)&ws[tr * 3 + tc][0];
#pragma unroll
            for (int k = 0; k < 4; k++) {
                float4 xv = xp[icq * 4 + k];
                float4 wv = wp[icq * 4 + k];
                acc = fmaf(xv.x, wv.x, fmaf(xv.y, wv.y, fmaf(xv.z, wv.z, fmaf(xv.w, wv.w, acc))));
            }
        }
    }
    acc += __shfl_xor_sync(0xffffffffu, acc, 1);
    acc += __shfl_xor_sync(0xffffffffu, acc, 2);
    if (icq == 0) y[(r0 << 5) + c] = acc + bias[0];
}

// ---------------- fused SSM cell step (drifting frame, in-place state) ----------------
// Block = 128 = 2 px x 64 d (warp = 32 consecutive d, coalesced state lines). grid = 512.
template <bool FIRST, bool DOY>
__global__ __launch_bounds__(128) void cell_step(const float* __restrict__ u,
                                                 const float* __restrict__ cc,
                                                 const float* __restrict__ Dskip,
                                                 const float* __restrict__ dtp,
                                                 int tau, float* __restrict__ ymax)
{
    const int tid = threadIdx.x;
    const int d = tid & 63;
    const int p = blockIdx.x * 2 + (tid >> 6);
    const int h = p >> 5, w = p & 31;

    float xx = cc[p * 96 + d] + dtp[0];
    float delta = (xx > 20.f) ? xx : log1pf(expf(xx));   // softplus
    const float ud = u[p * 64 + d];

    float ab[DS], bu[DS], cv[DS];
    if (g_uniA) {
        // all A[d][n] identical -> one exp instead of 16 (generic path below otherwise)
        float a = g_A[d];
        float e = __expf(delta * a);
        float f = (e - 1.f) * g_rA[d] * ud;
#pragma unroll
        for (int n = 0; n < DS; n++) {
            ab[n] = e;
            bu[n] = f * cc[p * 96 + 64 + n];
            if (DOY) cv[n] = cc[p * 96 + 80 + n];
        }
    } else {
#pragma unroll
        for (int n = 0; n < DS; n++) {
            float a = g_A[n * 64 + d];
            float e = __expf(delta * a);
            ab[n] = e;
            bu[n] = (e - 1.f) * g_rA[n * 64 + d] * cc[p * 96 + 64 + n] * ud;
            if (DOY) cv[n] = cc[p * 96 + 80 + n];
        }
    }

    float best = -1e30f;
#pragma unroll 1
    for (int v = 0; v < NV; v++) {
        int v5 = v / 5;
        int vx = v5 - 2;
        int vy = (v - v5 * 5) - 2;
        int qh = (h + tau * vy) & 31;
        int qw = (w + tau * vx) & 31;
        float* sp = g_state + (((size_t)v * DS * HW) + (size_t)((qh << 5) + qw)) * 64 + d;
        float acc = 0.f;
#pragma unroll
        for (int n = 0; n < DS; n++) {
            float s = FIRST ? bu[n] : fmaf(ab[n], sp[(size_t)n * HW * 64], bu[n]);
            sp[(size_t)n * HW * 64] = s;
            if (DOY) acc = fmaf(s, cv[n], acc);
        }
        if (DOY) best = fmaxf(best, acc);
    }
    if (DOY) ymax[p * 64 + d] = fmaf(Dskip[d], ud, best);
}

// ---------------- launch ----------------
extern "C" void kernel_launch(void* const* d_in, const int* in_sizes, int n_in,
                              void* d_out, int out_size)
{
    const float* input_seq = (const float*)d_in[0];
    const float* enc_w1 = (const float*)d_in[1];
    const float* enc_b1 = (const float*)d_in[2];
    const float* enc_w2 = (const float*)d_in[3];
    const float* enc_b2 = (const float*)d_in[4];
    const float* wd     = (const float*)d_in[5];
    const float* bd     = (const float*)d_in[6];
    const float* wB     = (const float*)d_in[7];
    const float* wC     = (const float*)d_in[8];
    const float* logA   = (const float*)d_in[9];
    const float* Dskip  = (const float*)d_in[10];
    const float* dt_inv = (const float*)d_in[11];
    const float* dec_w1 = (const float*)d_in[12];
    const float* dec_b1 = (const float*)d_in[13];
    const float* dec_w2 = (const float*)d_in[14];
    const float* dec_b2 = (const float*)d_in[15];
    const float* dec_w3 = (const float*)d_in[16];
    const float* dec_b3 = (const float*)d_in[17];
    float* out = (float*)d_out;

    float *p_u, *p_e1, *p_cc, *p_wpack, *p_wenc2, *p_wdec1, *p_wdec2, *p_bpack;
    float *p_ymax, *p_d1, *p_d2;
    cudaGetSymbolAddress((void**)&p_u, g_u);
    cudaGetSymbolAddress((void**)&p_e1, g_e1);
    cudaGetSymbolAddress((void**)&p_cc, g_cc);
    cudaGetSymbolAddress((void**)&p_wpack, g_wpack);
    cudaGetSymbolAddress((void**)&p_wenc2, g_wenc2);
    cudaGetSymbolAddress((void**)&p_wdec1, g_wdec1);
    cudaGetSymbolAddress((void**)&p_wdec2, g_wdec2);
    cudaGetSymbolAddress((void**)&p_bpack, g_bpack);
    cudaGetSymbolAddress((void**)&p_ymax, g_ymax);
    cudaGetSymbolAddress((void**)&p_d1, g_d1);
    cudaGetSymbolAddress((void**)&p_d2, g_d2);

    pack_all<<<651, 256>>>(wd, bd, wB, wC, logA, enc_w2, dec_w1, dec_w2);
    check_uni<<<1, 256>>>(logA);

    // ---- encode: batched over 4 frames ----
    conv1_cl<<<dim3(8, 16, TIN), 128>>>(input_seq, enc_w1, enc_b1, p_e1);
    conv8<true><<<dim3(32, 8, TIN), 64>>>(p_e1, p_wenc2, enc_b2, p_u, DM);
    conv8<false><<<dim3(32, 12, TIN), 64>>>(p_u, p_wpack, p_bpack, p_cc, 96);
    for (int t = 0; t < TIN; t++) {
        const float* ut = p_u + (size_t)t * HW * DM;
        const float* ct = p_cc + (size_t)t * HW * 96;
        if (t == 0)
            cell_step<true, false><<<512, 128>>>(ut, ct, Dskip, dt_inv, 1, nullptr);
        else
            cell_step<false, false><<<512, 128>>>(ut, ct, Dskip, dt_inv, t + 1, nullptr);
    }

    // ---- decode ----
    int steps = out_size / HW;
    for (int t = 0; t < steps; t++) {
        const float* src = (t == 0) ? (input_seq + 3 * HW) : (out + (size_t)(t - 1) * HW);
        conv1_cl<<<dim3(8, 16, 1), 128>>>(src, enc_w1, enc_b1, p_e1);
        conv8<true><<<dim3(32, 8, 1), 64>>>(p_e1, p_wenc2, enc_b2, p_u, DM);
        conv8<false><<<dim3(32, 12, 1), 64>>>(p_u, p_wpack, p_bpack, p_cc, 96);
        cell_step<false, true><<<512, 128>>>(p_u, p_cc, Dskip, dt_inv, TIN + 1 + t, p_ymax);
        conv8<true><<<dim3(32, 8, 1), 64>>>(p_ymax, p_wdec1, dec_b1, p_d1, DM);
        conv8<true><<<dim3(32, 8, 1), 64>>>(p_d1, p_wdec2, dec_b2, p_d2, DM);
        conv_out<<<32, 128>>>(p_d2, dec_w3, dec_b3, out + (size_t)t * HW);
    }
}

// round 4
// speedup vs baseline: 1.0286x; 1.0286x over previous
#include <cuda_runtime.h>
#include <math.h>

#define HW   1024
#define DM   64
#define DS   16
#define NV   25
#define TIN  4

// ---------------- scratch (static device globals; no allocation) ----------------
__device__ __align__(128) float g_state[(size_t)NV * DS * HW * DM];   // [v][n][q][d], ~105 MB
__device__ __align__(128) float g_u[TIN * HW * DM];
__device__ __align__(128) float g_e1[TIN * HW * DM];
__device__ __align__(128) float g_cc[TIN * HW * 96];                  // [t][px][dconv|B|C]
__device__ __align__(128) float g_wpack[96 * 576];                    // wd|wB|wC as [oc][tap][ic]
__device__ __align__(128) float g_wenc2[64 * 576];
__device__ __align__(128) float g_wdec1[64 * 576];
__device__ __align__(128) float g_wdec2[64 * 576];
__device__ __align__(128) float g_bpack[96];
__device__ __align__(128) float g_A[DS * DM];                         // A[n][d]
__device__ __align__(128) float g_rA[DS * DM];
__device__ int   g_uniA;
__device__ __align__(128) float g_ymax[HW * DM];
__device__ __align__(128) float g_d1[HW * DM];
__device__ __align__(128) float g_d2[HW * DM];

// ---------------- pack: weight transposes + bias + A fields ----------------
__global__ void pack_all(const float* __restrict__ wd, const float* __restrict__ bd,
                         const float* __restrict__ wB, const float* __restrict__ wC,
                         const float* __restrict__ logA,
                         const float* __restrict__ ew2, const float* __restrict__ dw1,
                         const float* __restrict__ dw2)
{
    int k = blockIdx.x * 256 + threadIdx.x;
    const int R0 = 96 * 576;
    const int R1 = R0 + 3 * 64 * 576;
    if (k < R0) {
        int oc = k / 576, rem = k - oc * 576;
        int tap = rem >> 6, ic = rem & 63;
        float v;
        if (oc < 64)      v = wd[oc * 576 + ic * 9 + tap];
        else if (oc < 80) v = wB[(oc - 64) * 576 + ic * 9 + tap];
        else              v = wC[(oc - 80) * 576 + ic * 9 + tap];
        g_wpack[k] = v;
    } else if (k < R1) {
        int k2 = k - R0;
        int which = k2 / (64 * 576);
        int k3 = k2 - which * (64 * 576);
        int oc = k3 / 576, rem = k3 - oc * 576;
        int tap = rem >> 6, ic = rem & 63;
        const float* s = (which == 0) ? ew2 : ((which == 1) ? dw1 : dw2);
        float v = s[oc * 576 + ic * 9 + tap];
        if (which == 0) g_wenc2[k3] = v;
        else if (which == 1) g_wdec1[k3] = v;
        else g_wdec2[k3] = v;
    }
    if (k < DM)       g_bpack[k] = bd[k];
    else if (k < 96)  g_bpack[k] = 0.f;
    if (k < DS * DM) {
        int n = k >> 6, d = k & 63;
        float a = -expf(logA[d * DS + n]);
        g_A[k] = a;
        g_rA[k] = 1.f / a;
    }
}

__global__ void check_uni(const float* __restrict__ logA)
{
    __shared__ int ok;
    if (threadIdx.x == 0) ok = 1;
    __syncthreads();
    float a0 = logA[0];
    for (int i = threadIdx.x; i < DM * DS; i += 256)
        if (logA[i] != a0) atomicAnd(&ok, 0);
    __syncthreads();
    if (threadIdx.x == 0) g_uniA = ok;
}

// ---------------- channel-last circular 3x3 conv, IC=64 ----------------
// Block = 128 thr = 32 px (1 row) x 4 warp-uniform oc-quads (16 oc/block).
// x staged in smem (17-pad float4); w read via warp-uniform __ldg float4 (no staging).
// grid = (32 rows, OC/16, z). Fully unrolled: ptxas pipelines loads ahead of FMA chains.
template <bool RELU>
__global__ __launch_bounds__(128) void conv16(const float* __restrict__ x,
                                              const float* __restrict__ wgt,
                                              const float* __restrict__ bias,
                                              float* __restrict__ y, int OC)
{
    __shared__ float4 xs[3 * 32 * 17];    // 26 KB
    const int tid = threadIdx.x;
    const int obase = blockIdx.y * 16;
    const int r0 = blockIdx.x;
    x += (size_t)blockIdx.z * DM * HW;
    y += (size_t)blockIdx.z * (size_t)OC * HW;

    const float4* x4 = (const float4*)x;
    for (int k = tid; k < 3 * 32 * 16; k += 128) {
        int lr = k >> 9; int rem = k & 511; int c = rem >> 4; int icv = rem & 15;
        int row = (r0 - 1 + lr) & 31;
        xs[(lr * 32 + c) * 17 + icv] = x4[(((row << 5) + c) << 4) + icv];
    }
    __syncthreads();

    const int q = tid >> 5;            // warp-uniform
    const int c = tid & 31;
    const int cm = (c + 31) & 31, cp = (c + 1) & 31;
    const int oc0 = obase + q * 4;

    float a0 = __ldg(bias + oc0 + 0);
    float a1 = __ldg(bias + oc0 + 1);
    float a2 = __ldg(bias + oc0 + 2);
    float a3 = __ldg(bias + oc0 + 3);
    const float4* w0 = (const float4*)wgt + (size_t)(oc0 + 0) * 144;
    const float4* w1 = (const float4*)wgt + (size_t)(oc0 + 1) * 144;
    const float4* w2 = (const float4*)wgt + (size_t)(oc0 + 2) * 144;
    const float4* w3 = (const float4*)wgt + (size_t)(oc0 + 3) * 144;

#pragma unroll
    for (int tap = 0; tap < 9; tap++) {
        const int tr = tap / 3, tc = tap - tr * 3;
        const int cx = (tc == 0) ? cm : ((tc == 1) ? c : cp);
        const float4* xp = &xs[(tr * 32 + cx) * 17];
#pragma unroll
        for (int icv = 0; icv < 16; icv++) {
            float4 xv = xp[icv];
            float4 v0 = __ldg(w0 + tap * 16 + icv);
            float4 v1 = __ldg(w1 + tap * 16 + icv);
            float4 v2 = __ldg(w2 + tap * 16 + icv);
            float4 v3 = __ldg(w3 + tap * 16 + icv);
            a0 = fmaf(xv.x, v0.x, fmaf(xv.y, v0.y, fmaf(xv.z, v0.z, fmaf(xv.w, v0.w, a0))));
            a1 = fmaf(xv.x, v1.x, fmaf(xv.y, v1.y, fmaf(xv.z, v1.z, fmaf(xv.w, v1.w, a1))));
            a2 = fmaf(xv.x, v2.x, fmaf(xv.y, v2.y, fmaf(xv.z, v2.z, fmaf(xv.w, v2.w, a2))));
            a3 = fmaf(xv.x, v3.x, fmaf(xv.y, v3.y, fmaf(xv.z, v3.z, fmaf(xv.w, v3.w, a3))));
        }
    }
    if (RELU) {
        a0 = fmaxf(a0, 0.f); a1 = fmaxf(a1, 0.f);
        a2 = fmaxf(a2, 0.f); a3 = fmaxf(a3, 0.f);
    }
    const int px = (r0 << 5) + c;
    float4 o; o.x = a0; o.y = a1; o.z = a2; o.w = a3;
    *(float4*)&y[(size_t)px * OC + oc0] = o;
}

// ---------------- channel-last conv, IC=1 (encoder stage 1) ----------------
__global__ __launch_bounds__(128) void conv1_cl(const float* __restrict__ x,
                                                const float* __restrict__ wgt,
                                                const float* __restrict__ bias,
                                                float* __restrict__ y)
{
    __shared__ float xs[6 * 32];
    __shared__ float ws[4][9];
    __shared__ float bs[4];
    const int tid = threadIdx.x;
    const int obase = blockIdx.y * 4;
    x += blockIdx.z * HW;
    y += (size_t)blockIdx.z * DM * HW;
    const int r0 = blockIdx.x * 4;
    for (int k = tid; k < 6 * 32; k += 128) {
        int lr = k >> 5, c = k & 31;
        xs[k] = x[(((r0 - 1 + lr) & 31) << 5) + c];
    }
    if (tid < 36) ws[tid / 9][tid % 9] = wgt[(obase + tid / 9) * 9 + tid % 9];
    if (tid < 4)  bs[tid] = bias[obase + tid];
    __syncthreads();

    const int hl = tid >> 5, c = tid & 31;
    const int cm = (c + 31) & 31, cp = (c + 1) & 31;
    float xv[9];
#pragma unroll
    for (int tr = 0; tr < 3; tr++) {
        xv[tr * 3 + 0] = xs[(hl + tr) * 32 + cm];
        xv[tr * 3 + 1] = xs[(hl + tr) * 32 + c];
        xv[tr * 3 + 2] = xs[(hl + tr) * 32 + cp];
    }
    float4 o; float* op = &o.x;
#pragma unroll
    for (int j = 0; j < 4; j++) {
        float a = bs[j];
#pragma unroll
        for (int t9 = 0; t9 < 9; t9++) a = fmaf(xv[t9], ws[j][t9], a);
        op[j] = fmaxf(a, 0.f);
    }
    const int px = blockIdx.x * 128 + tid;
    *(float4*)&y[(size_t)px * DM + obase] = o;
}

// ---------------- channel-last conv, OC=1 (decoder out) ----------------
__global__ __launch_bounds__(128) void conv_out(const float* __restrict__ x,
                                                const float* __restrict__ wgt,
                                                const float* __restrict__ bias,
                                                float* __restrict__ y)
{
    __shared__ float4 xs[3 * 32 * 17];
    __shared__ float  ws[9][64];
    const int tid = threadIdx.x;
    const int r0 = blockIdx.x;
    const float4* x4 = (const float4*)x;
    for (int k = tid; k < 3 * 32 * 16; k += 128) {
        int lr = k >> 9; int rem = k & 511; int c = rem >> 4; int icv = rem & 15;
        int row = (r0 - 1 + lr) & 31;
        xs[(lr * 32 + c) * 17 + icv] = x4[(((row << 5) + c) << 4) + icv];
    }
    for (int k = tid; k < 576; k += 128) {
        int tap = k >> 6, ic = k & 63;
        ws[tap][ic] = wgt[ic * 9 + tap];
    }
    __syncthreads();

    const int icq = tid & 3, c = tid >> 2;
    const int cm = (c + 31) & 31, cp = (c + 1) & 31;
    float acc = 0.f;
#pragma unroll
    for (int tr = 0; tr < 3; tr++) {
#pragma unroll
        for (int tc = 0; tc < 3; tc++) {
            const int cx = (tc == 0) ? cm : ((tc == 1) ? c : cp);
            const float4* xp = &xs[(tr * 32 + cx) * 17];
            const float4* wp = (const float4*)&ws[tr * 3 + tc][0];
#pragma unroll
            for (int k = 0; k < 4; k++) {
                float4 xv = xp[icq * 4 + k];
                float4 wv = wp[icq * 4 + k];
                acc = fmaf(xv.x, wv.x, fmaf(xv.y, wv.y, fmaf(xv.z, wv.z, fmaf(xv.w, wv.w, acc))));
            }
        }
    }
    acc += __shfl_xor_sync(0xffffffffu, acc, 1);
    acc += __shfl_xor_sync(0xffffffffu, acc, 2);
    if (icq == 0) y[(r0 << 5) + c] = acc + bias[0];
}

// ---------------- fused SSM cell step (drifting frame, in-place, d-quad vectorized) ----
// Block = 128 thr = 8 px x 16 d-quads (thread owns 4 consecutive d -> LDG.128/STG.128).
// grid = 128.
template <bool FIRST, bool DOY>
__global__ __launch_bounds__(128) void cell_step(const float* __restrict__ u,
                                                 const float* __restrict__ cc,
                                                 const float* __restrict__ Dskip,
                                                 const float* __restrict__ dtp,
                                                 int tau, float* __restrict__ ymax)
{
    const int tid = threadIdx.x;
    const int d0 = (tid & 15) * 4;
    const int p = blockIdx.x * 8 + (tid >> 4);
    const int h = p >> 5, w = p & 31;
    const float dti = dtp[0];

    float4 xx = *(const float4*)&cc[p * 96 + d0];
    float4 delta;
    {
        float t0 = xx.x + dti, t1 = xx.y + dti, t2 = xx.z + dti, t3 = xx.w + dti;
        delta.x = (t0 > 20.f) ? t0 : log1pf(expf(t0));
        delta.y = (t1 > 20.f) ? t1 : log1pf(expf(t1));
        delta.z = (t2 > 20.f) ? t2 : log1pf(expf(t2));
        delta.w = (t3 > 20.f) ? t3 : log1pf(expf(t3));
    }
    float4 ud = *(const float4*)&u[p * 64 + d0];

    float4 ab, bu[DS];
    float cv[DS];
    if (g_uniA) {
        float4 a  = *(const float4*)&g_A[d0];
        float4 ra = *(const float4*)&g_rA[d0];
        ab.x = __expf(delta.x * a.x);
        ab.y = __expf(delta.y * a.y);
        ab.z = __expf(delta.z * a.z);
        ab.w = __expf(delta.w * a.w);
        float4 f;
        f.x = (ab.x - 1.f) * ra.x * ud.x;
        f.y = (ab.y - 1.f) * ra.y * ud.y;
        f.z = (ab.z - 1.f) * ra.z * ud.z;
        f.w = (ab.w - 1.f) * ra.w * ud.w;
#pragma unroll
        for (int n = 0; n < DS; n++) {
            float b = cc[p * 96 + 64 + n];
            bu[n].x = f.x * b; bu[n].y = f.y * b; bu[n].z = f.z * b; bu[n].w = f.w * b;
            if (DOY) cv[n] = cc[p * 96 + 80 + n];
        }
        float4 best = {-1e30f, -1e30f, -1e30f, -1e30f};
#pragma unroll 1
        for (int v = 0; v < NV; v++) {
            int v5 = v / 5;
            int vx = v5 - 2;
            int vy = (v - v5 * 5) - 2;
            int qh = (h + tau * vy) & 31;
            int qw = (w + tau * vx) & 31;
            float* sp = g_state + (((size_t)v * DS * HW) + (size_t)((qh << 5) + qw)) * 64 + d0;
            float4 acc = {0.f, 0.f, 0.f, 0.f};
#pragma unroll
            for (int n = 0; n < DS; n++) {
                float4* sq = (float4*)(sp + (size_t)n * HW * 64);
                float4 s;
                if (FIRST) {
                    s = bu[n];
                } else {
                    float4 o = *sq;
                    s.x = fmaf(ab.x, o.x, bu[n].x);
                    s.y = fmaf(ab.y, o.y, bu[n].y);
                    s.z = fmaf(ab.z, o.z, bu[n].z);
                    s.w = fmaf(ab.w, o.w, bu[n].w);
                }
                *sq = s;
                if (DOY) {
                    acc.x = fmaf(s.x, cv[n], acc.x);
                    acc.y = fmaf(s.y, cv[n], acc.y);
                    acc.z = fmaf(s.z, cv[n], acc.z);
                    acc.w = fmaf(s.w, cv[n], acc.w);
                }
            }
            if (DOY) {
                best.x = fmaxf(best.x, acc.x);
                best.y = fmaxf(best.y, acc.y);
                best.z = fmaxf(best.z, acc.z);
                best.w = fmaxf(best.w, acc.w);
            }
        }
        if (DOY) {
            float4 dk = *(const float4*)&Dskip[d0];
            float4 o;
            o.x = fmaf(dk.x, ud.x, best.x);
            o.y = fmaf(dk.y, ud.y, best.y);
            o.z = fmaf(dk.z, ud.z, best.z);
            o.w = fmaf(dk.w, ud.w, best.w);
            *(float4*)&ymax[p * 64 + d0] = o;
        }
    } else {
        // generic fallback (correct for any A; may spill — not the hot path)
        float4 abn[DS];
#pragma unroll
        for (int n = 0; n < DS; n++) {
            float4 a, ra;
            a.x = g_A[n * 64 + d0 + 0]; a.y = g_A[n * 64 + d0 + 1];
            a.z = g_A[n * 64 + d0 + 2]; a.w = g_A[n * 64 + d0 + 3];
            ra.x = g_rA[n * 64 + d0 + 0]; ra.y = g_rA[n * 64 + d0 + 1];
            ra.z = g_rA[n * 64 + d0 + 2]; ra.w = g_rA[n * 64 + d0 + 3];
            float4 e;
            e.x = __expf(delta.x * a.x); e.y = __expf(delta.y * a.y);
            e.z = __expf(delta.z * a.z); e.w = __expf(delta.w * a.w);
            abn[n] = e;
            float b = cc[p * 96 + 64 + n];
            bu[n].x = (e.x - 1.f) * ra.x * ud.x * b;
            bu[n].y = (e.y - 1.f) * ra.y * ud.y * b;
            bu[n].z = (e.z - 1.f) * ra.z * ud.z * b;
            bu[n].w = (e.w - 1.f) * ra.w * ud.w * b;
            if (DOY) cv[n] = cc[p * 96 + 80 + n];
        }
        float4 best = {-1e30f, -1e30f, -1e30f, -1e30f};
#pragma unroll 1
        for (int v = 0; v < NV; v++) {
            int v5 = v / 5;
            int vx = v5 - 2;
            int vy = (v - v5 * 5) - 2;
            int qh = (h + tau * vy) & 31;
            int qw = (w + tau * vx) & 31;
            float* sp = g_state + (((size_t)v * DS * HW) + (size_t)((qh << 5) + qw)) * 64 + d0;
            float4 acc = {0.f, 0.f, 0.f, 0.f};
#pragma unroll
            for (int n = 0; n < DS; n++) {
                float4* sq = (float4*)(sp + (size_t)n * HW * 64);
                float4 s;
                if (FIRST) {
                    s = bu[n];
                } else {
                    float4 o = *sq;
                    s.x = fmaf(abn[n].x, o.x, bu[n].x);
                    s.y = fmaf(abn[n].y, o.y, bu[n].y);
                    s.z = fmaf(abn[n].z, o.z, bu[n].z);
                    s.w = fmaf(abn[n].w, o.w, bu[n].w);
                }
                *sq = s;
                if (DOY) {
                    acc.x = fmaf(s.x, cv[n], acc.x);
                    acc.y = fmaf(s.y, cv[n], acc.y);
                    acc.z = fmaf(s.z, cv[n], acc.z);
                    acc.w = fmaf(s.w, cv[n], acc.w);
                }
            }
            if (DOY) {
                best.x = fmaxf(best.x, acc.x);
                best.y = fmaxf(best.y, acc.y);
                best.z = fmaxf(best.z, acc.z);
                best.w = fmaxf(best.w, acc.w);
            }
        }
        if (DOY) {
            float4 dk = *(const float4*)&Dskip[d0];
            float4 o;
            o.x = fmaf(dk.x, ud.x, best.x);
            o.y = fmaf(dk.y, ud.y, best.y);
            o.z = fmaf(dk.z, ud.z, best.z);
            o.w = fmaf(dk.w, ud.w, best.w);
            *(float4*)&ymax[p * 64 + d0] = o;
        }
    }
}

// ---------------- launch ----------------
extern "C" void kernel_launch(void* const* d_in, const int* in_sizes, int n_in,
                              void* d_out, int out_size)
{
    const float* input_seq = (const float*)d_in[0];
    const float* enc_w1 = (const float*)d_in[1];
    const float* enc_b1 = (const float*)d_in[2];
    const float* enc_w2 = (const float*)d_in[3];
    const float* enc_b2 = (const float*)d_in[4];
    const float* wd     = (const float*)d_in[5];
    const float* bd     = (const float*)d_in[6];
    const float* wB     = (const float*)d_in[7];
    const float* wC     = (const float*)d_in[8];
    const float* logA   = (const float*)d_in[9];
    const float* Dskip  = (const float*)d_in[10];
    const float* dt_inv = (const float*)d_in[11];
    const float* dec_w1 = (const float*)d_in[12];
    const float* dec_b1 = (const float*)d_in[13];
    const float* dec_w2 = (const float*)d_in[14];
    const float* dec_b2 = (const float*)d_in[15];
    const float* dec_w3 = (const float*)d_in[16];
    const float* dec_b3 = (const float*)d_in[17];
    float* out = (float*)d_out;

    float *p_u, *p_e1, *p_cc, *p_wpack, *p_wenc2, *p_wdec1, *p_wdec2, *p_bpack;
    float *p_ymax, *p_d1, *p_d2;
    cudaGetSymbolAddress((void**)&p_u, g_u);
    cudaGetSymbolAddress((void**)&p_e1, g_e1);
    cudaGetSymbolAddress((void**)&p_cc, g_cc);
    cudaGetSymbolAddress((void**)&p_wpack, g_wpack);
    cudaGetSymbolAddress((void**)&p_wenc2, g_wenc2);
    cudaGetSymbolAddress((void**)&p_wdec1, g_wdec1);
    cudaGetSymbolAddress((void**)&p_wdec2, g_wdec2);
    cudaGetSymbolAddress((void**)&p_bpack, g_bpack);
    cudaGetSymbolAddress((void**)&p_ymax, g_ymax);
    cudaGetSymbolAddress((void**)&p_d1, g_d1);
    cudaGetSymbolAddress((void**)&p_d2, g_d2);

    pack_all<<<651, 256>>>(wd, bd, wB, wC, logA, enc_w2, dec_w1, dec_w2);
    check_uni<<<1, 256>>>(logA);

    // ---- encode: batched over 4 frames ----
    conv1_cl<<<dim3(8, 16, TIN), 128>>>(input_seq, enc_w1, enc_b1, p_e1);
    conv16<true><<<dim3(32, 4, TIN), 128>>>(p_e1, p_wenc2, enc_b2, p_u, DM);
    conv16<false><<<dim3(32, 6, TIN), 128>>>(p_u, p_wpack, p_bpack, p_cc, 96);
    for (int t = 0; t < TIN; t++) {
        const float* ut = p_u + (size_t)t * HW * DM;
        const float* ct = p_cc + (size_t)t * HW * 96;
        if (t == 0)
            cell_step<true, false><<<128, 128>>>(ut, ct, Dskip, dt_inv, 1, nullptr);
        else
            cell_step<false, false><<<128, 128>>>(ut, ct, Dskip, dt_inv, t + 1, nullptr);
    }

    // ---- decode ----
    int steps = out_size / HW;
    for (int t = 0; t < steps; t++) {
        const float* src = (t == 0) ? (input_seq + 3 * HW) : (out + (size_t)(t - 1) * HW);
        conv1_cl<<<dim3(8, 16, 1), 128>>>(src, enc_w1, enc_b1, p_e1);
        conv16<true><<<dim3(32, 4, 1), 128>>>(p_e1, p_wenc2, enc_b2, p_u, DM);
        conv16<false><<<dim3(32, 6, 1), 128>>>(p_u, p_wpack, p_bpack, p_cc, 96);
        cell_step<false, true><<<128, 128>>>(p_u, p_cc, Dskip, dt_inv, TIN + 1 + t, p_ymax);
        conv16<true><<<dim3(32, 4, 1), 128>>>(p_ymax, p_wdec1, dec_b1, p_d1, DM);
        conv16<true><<<dim3(32, 4, 1), 128>>>(p_d1, p_wdec2, dec_b2, p_d2, DM);
        conv_out<<<32, 128>>>(p_d2, dec_w3, dec_b3, out + (size_t)t * HW);
    }
}

// round 5
// speedup vs baseline: 2.4111x; 2.3440x over previous
#include <cuda_runtime.h>
#include <math.h>

#define HW   1024
#define DM   64
#define DS   16
#define NV   25
#define TIN  4
#define MAXS 8

// ---------------- scratch (static device globals; no allocation) ----------------
__device__ __align__(128) float g_u[TIN * HW * DM];
__device__ __align__(128) float g_e1[TIN * HW * DM];
__device__ __align__(128) float g_cc[TIN * HW * 96];            // [t][px][dconv|B|C]
__device__ __align__(128) float g_wpack[96 * DM * 9];           // wd|wB|wC raw concat [oc][ic*9]
__device__ __align__(128) float g_bpack[96];
__device__ __align__(128) float g_A[DS * DM];                   // A[n][d] = -exp(logA[d][n])
__device__ __align__(128) float g_rA[DS * DM];
__device__ int   g_uniA;
// history fields, slot s-1 for step s = 1..8
__device__ __align__(128) float g_ef[MAXS * HW * DM * 2];       // [slot][p][dq][{e4,f4}] float4 pairs
__device__ __align__(128) float g_dl[MAXS * HW * DM];           // delta (generic fallback)
__device__ __align__(128) float g_uf[MAXS * HW * DM];           // u history (generic fallback)
__device__ __align__(128) float g_Bf[MAXS * HW * DS];           // B fields [slot][p][n]
__device__ __align__(128) float g_ymax[HW * DM];
__device__ __align__(128) float g_d1[HW * DM];
__device__ __align__(128) float g_d2[HW * DM];

// ---------------- pack weights (raw concat) + A fields ----------------
__global__ void pack_w(const float* __restrict__ wd, const float* __restrict__ bd,
                       const float* __restrict__ wB, const float* __restrict__ wC,
                       const float* __restrict__ logA)
{
    int k = blockIdx.x * 256 + threadIdx.x;
    const int W1 = DM * DM * 9;
    const int W2 = DS * DM * 9;
    if (k < W1)                 g_wpack[k] = wd[k];
    else if (k < W1 + W2)       g_wpack[k] = wB[k - W1];
    else if (k < W1 + 2 * W2)   g_wpack[k] = wC[k - W1 - W2];
    if (k < DM)                 g_bpack[k] = bd[k];
    else if (k < 96)            g_bpack[k] = 0.f;
    if (k < DS * DM) {
        int n = k >> 6, d = k & 63;
        float a = -expf(logA[d * DS + n]);
        g_A[k] = a;
        g_rA[k] = 1.f / a;
    }
}

// row-wise uniformity: A[d][n] == A[d][0] for all n (fast path requirement)
__global__ void check_uni(const float* __restrict__ logA)
{
    __shared__ int ok;
    if (threadIdx.x == 0) ok = 1;
    __syncthreads();
    bool bad = false;
    for (int i = threadIdx.x; i < DM * DS; i += 256)
        if (logA[i] != logA[(i / DS) * DS]) bad = true;
    if (bad) atomicAnd(&ok, 0);
    __syncthreads();
    if (threadIdx.x == 0) g_uniA = ok;
}

// ---------------- channel-last circular 3x3 conv, IC=64 (R2-proven) ----------------
template <bool RELU>
__global__ __launch_bounds__(64) void conv_cl(const float* __restrict__ x,
                                              const float* __restrict__ wgt,
                                              const float* __restrict__ bias,
                                              float* __restrict__ y, int OC)
{
    __shared__ float4 xs[3 * 32 * 17];
    __shared__ float  ws[4][9][64];
    __shared__ float  bs[4];
    const int tid = threadIdx.x;
    const int obase = blockIdx.y * 4;
    const int r0 = blockIdx.x;
    x += (size_t)blockIdx.z * DM * HW;
    y += (size_t)blockIdx.z * (size_t)OC * HW;

    const float4* x4 = (const float4*)x;
    for (int k = tid; k < 3 * 32 * 16; k += 64) {
        int lr = k >> 9; int rem = k & 511; int c = rem >> 4; int icv = rem & 15;
        int row = (r0 - 1 + lr) & 31;
        xs[(lr * 32 + c) * 17 + icv] = x4[(((row << 5) + c) << 4) + icv];
    }
    for (int k = tid; k < 4 * 9 * 64; k += 64) {
        int ocl = k / 576; int rem = k - ocl * 576; int tap = rem >> 6; int ic = rem & 63;
        ws[ocl][tap][ic] = wgt[(obase + ocl) * 576 + ic * 9 + tap];
    }
    if (tid < 4) bs[tid] = bias[obase + tid];
    __syncthreads();

    const int ocp = tid >> 5;
    const int c   = tid & 31;
    const int cm = (c + 31) & 31, cp = (c + 1) & 31;
    const int oc0 = obase + ocp * 2;
    float a0 = bs[ocp * 2], a1 = bs[ocp * 2 + 1];
    const float4* w0 = (const float4*)&ws[ocp * 2][0][0];
    const float4* w1 = (const float4*)&ws[ocp * 2 + 1][0][0];

#pragma unroll
    for (int tr = 0; tr < 3; tr++) {
#pragma unroll
        for (int tc = 0; tc < 3; tc++) {
            const int cx = (tc == 0) ? cm : ((tc == 1) ? c : cp);
            const float4* xp  = &xs[(tr * 32 + cx) * 17];
            const float4* wp0 = w0 + (tr * 3 + tc) * 16;
            const float4* wp1 = w1 + (tr * 3 + tc) * 16;
#pragma unroll
            for (int icv = 0; icv < 16; icv++) {
                float4 xv = xp[icv];
                float4 v0 = wp0[icv];
                float4 v1 = wp1[icv];
                a0 = fmaf(xv.x, v0.x, fmaf(xv.y, v0.y, fmaf(xv.z, v0.z, fmaf(xv.w, v0.w, a0))));
                a1 = fmaf(xv.x, v1.x, fmaf(xv.y, v1.y, fmaf(xv.z, v1.z, fmaf(xv.w, v1.w, a1))));
            }
        }
    }
    if (RELU) { a0 = fmaxf(a0, 0.f); a1 = fmaxf(a1, 0.f); }
    const int px = (r0 << 5) + c;
    float2 o; o.x = a0; o.y = a1;
    *(float2*)&y[(size_t)px * OC + oc0] = o;
}

// ---------------- channel-last conv, IC=1 ----------------
__global__ __launch_bounds__(128) void conv1_cl(const float* __restrict__ x,
                                                const float* __restrict__ wgt,
                                                const float* __restrict__ bias,
                                                float* __restrict__ y)
{
    __shared__ float xs[6 * 32];
    __shared__ float ws[4][9];
    __shared__ float bs[4];
    const int tid = threadIdx.x;
    const int obase = blockIdx.y * 4;
    x += blockIdx.z * HW;
    y += (size_t)blockIdx.z * DM * HW;
    const int r0 = blockIdx.x * 4;
    for (int k = tid; k < 6 * 32; k += 128) {
        int lr = k >> 5, c = k & 31;
        xs[k] = x[(((r0 - 1 + lr) & 31) << 5) + c];
    }
    if (tid < 36) ws[tid / 9][tid % 9] = wgt[(obase + tid / 9) * 9 + tid % 9];
    if (tid < 4)  bs[tid] = bias[obase + tid];
    __syncthreads();

    const int hl = tid >> 5, c = tid & 31;
    const int cm = (c + 31) & 31, cp = (c + 1) & 31;
    float xv[9];
#pragma unroll
    for (int tr = 0; tr < 3; tr++) {
        xv[tr * 3 + 0] = xs[(hl + tr) * 32 + cm];
        xv[tr * 3 + 1] = xs[(hl + tr) * 32 + c];
        xv[tr * 3 + 2] = xs[(hl + tr) * 32 + cp];
    }
    float4 o; float* op = &o.x;
#pragma unroll
    for (int j = 0; j < 4; j++) {
        float a = bs[j];
#pragma unroll
        for (int t9 = 0; t9 < 9; t9++) a = fmaf(xv[t9], ws[j][t9], a);
        op[j] = fmaxf(a, 0.f);
    }
    const int px = blockIdx.x * 128 + tid;
    *(float4*)&y[(size_t)px * DM + obase] = o;
}

// ---------------- channel-last conv, OC=1 ----------------
__global__ __launch_bounds__(128) void conv_out(const float* __restrict__ x,
                                                const float* __restrict__ wgt,
                                                const float* __restrict__ bias,
                                                float* __restrict__ y)
{
    __shared__ float4 xs[3 * 32 * 17];
    __shared__ float  ws[9][64];
    const int tid = threadIdx.x;
    const int r0 = blockIdx.x;
    const float4* x4 = (const float4*)x;
    for (int k = tid; k < 3 * 32 * 16; k += 128) {
        int lr = k >> 9; int rem = k & 511; int c = rem >> 4; int icv = rem & 15;
        int row = (r0 - 1 + lr) & 31;
        xs[(lr * 32 + c) * 17 + icv] = x4[(((row << 5) + c) << 4) + icv];
    }
    for (int k = tid; k < 576; k += 128) {
        int tap = k >> 6, ic = k & 63;
        ws[tap][ic] = wgt[ic * 9 + tap];
    }
    __syncthreads();

    const int icq = tid & 3, c = tid >> 2;
    const int cm = (c + 31) & 31, cp = (c + 1) & 31;
    float acc = 0.f;
#pragma unroll
    for (int tr = 0; tr < 3; tr++) {
#pragma unroll
        for (int tc = 0; tc < 3; tc++) {
            const int cx = (tc == 0) ? cm : ((tc == 1) ? c : cp);
            const float4* xp = &xs[(tr * 32 + cx) * 17];
            const float4* wp = (const float4*)&ws[tr * 3 + tc][0];
#pragma unroll
            for (int k = 0; k < 4; k++) {
                float4 xv = xp[icq * 4 + k];
                float4 wv = wp[icq * 4 + k];
                acc = fmaf(xv.x, wv.x, fmaf(xv.y, wv.y, fmaf(xv.z, wv.z, fmaf(xv.w, wv.w, acc))));
            }
        }
    }
    acc += __shfl_xor_sync(0xffffffffu, acc, 1);
    acc += __shfl_xor_sync(0xffffffffu, acc, 2);
    if (icq == 0) y[(r0 << 5) + c] = acc + bias[0];
}

__device__ __forceinline__ float sp_f(float x) { return (x > 20.f) ? x : log1pf(expf(x)); }

// ---------------- prep: compute e,f,delta,u,B fields for slot (encode steps) ----------
// grid (128, 1, NZ); block 128 = 8 px x 16 dq/n. slot = blockIdx.z.
__global__ __launch_bounds__(128) void prep(const float* __restrict__ cc,
                                            const float* __restrict__ u,
                                            const float* __restrict__ dtp)
{
    const int s = blockIdx.z;
    cc += (size_t)s * HW * 96;
    u  += (size_t)s * HW * 64;
    const int tid = threadIdx.x;
    const int pl = tid >> 4, dq = tid & 15;
    const int p = blockIdx.x * 8 + pl;
    const float dti = dtp[0];

    float4 dc = *(const float4*)&cc[p * 96 + dq * 4];
    float4 dl4;
    dl4.x = sp_f(dc.x + dti); dl4.y = sp_f(dc.y + dti);
    dl4.z = sp_f(dc.z + dti); dl4.w = sp_f(dc.w + dti);
    float4 a4  = *(const float4*)&g_A[dq * 4];     // n=0 row (uniA path)
    float4 ra4 = *(const float4*)&g_rA[dq * 4];
    float4 e4, f4;
    e4.x = __expf(dl4.x * a4.x); e4.y = __expf(dl4.y * a4.y);
    e4.z = __expf(dl4.z * a4.z); e4.w = __expf(dl4.w * a4.w);
    float4 u4 = *(const float4*)&u[p * 64 + dq * 4];
    f4.x = (e4.x - 1.f) * ra4.x * u4.x;
    f4.y = (e4.y - 1.f) * ra4.y * u4.y;
    f4.z = (e4.z - 1.f) * ra4.z * u4.z;
    f4.w = (e4.w - 1.f) * ra4.w * u4.w;

    float4* efp = (float4*)g_ef + (((size_t)s * HW + p) * 16 + dq) * 2;
    efp[0] = e4; efp[1] = f4;
    *(float4*)&g_dl[((size_t)s * HW + p) * 64 + dq * 4] = dl4;
    *(float4*)&g_uf[((size_t)s * HW + p) * 64 + dq * 4] = u4;
    g_Bf[((size_t)s * HW + p) * 16 + dq] = cc[p * 96 + 64 + dq];   // dq as n
}

// ---------------- fused y-kernel (decode step S = 5..8, 1-based) ----------------
// Computes own-step e/f/B/C, stores history fields, builds G in smem, evaluates
// y_max over v directly from history -- no SSM state anywhere.
// block 128 = 8 px x 16 dq; grid 128.
__global__ __launch_bounds__(128) void fused_y(const float* __restrict__ cc,
                                               const float* __restrict__ u,
                                               const float* __restrict__ Dskip,
                                               const float* __restrict__ dtp,
                                               int S, float* __restrict__ ymax)
{
    __shared__ float Bs[8][16], Cs[8][16];
    __shared__ float Gs[8][NV][MAXS];
    __shared__ float G0[8];
    const int tid = threadIdx.x;
    const int pl = tid >> 4, dq = tid & 15;
    const int p0 = blockIdx.x * 8;
    const int p = p0 + pl;
    const int h = p >> 5, w = p & 31;
    const int slotS = S - 1;
    const float dti = dtp[0];

    // own-step prep
    float4 dc = *(const float4*)&cc[p * 96 + dq * 4];
    float4 dl4;
    dl4.x = sp_f(dc.x + dti); dl4.y = sp_f(dc.y + dti);
    dl4.z = sp_f(dc.z + dti); dl4.w = sp_f(dc.w + dti);
    float4 a4  = *(const float4*)&g_A[dq * 4];
    float4 ra4 = *(const float4*)&g_rA[dq * 4];
    float4 e4o, f4o;
    e4o.x = __expf(dl4.x * a4.x); e4o.y = __expf(dl4.y * a4.y);
    e4o.z = __expf(dl4.z * a4.z); e4o.w = __expf(dl4.w * a4.w);
    float4 u4 = *(const float4*)&u[p * 64 + dq * 4];
    f4o.x = (e4o.x - 1.f) * ra4.x * u4.x;
    f4o.y = (e4o.y - 1.f) * ra4.y * u4.y;
    f4o.z = (e4o.z - 1.f) * ra4.z * u4.z;
    f4o.w = (e4o.w - 1.f) * ra4.w * u4.w;

    float4* efp = (float4*)g_ef + (((size_t)slotS * HW + p) * 16 + dq) * 2;
    efp[0] = e4o; efp[1] = f4o;
    *(float4*)&g_dl[((size_t)slotS * HW + p) * 64 + dq * 4] = dl4;
    *(float4*)&g_uf[((size_t)slotS * HW + p) * 64 + dq * 4] = u4;
    float bv = cc[p * 96 + 64 + dq];
    g_Bf[((size_t)slotS * HW + p) * 16 + dq] = bv;
    Bs[pl][dq] = bv;
    Cs[pl][dq] = cc[p * 96 + 80 + dq];
    __syncthreads();

    // G0 (k=0, shift 0, v-independent)
    if (tid < 8) {
        float s = 0.f;
#pragma unroll
        for (int n = 0; n < 16; n++) s += Bs[tid][n] * Cs[tid][n];
        G0[tid] = s;
    }
    // Gs[pl][v][k], k = 1..S-1 (history slot S-1-k)
    const int Sm1 = S - 1;
    const int tot = 8 * NV * Sm1;
    for (int idx = tid; idx < tot; idx += 128) {
        int i = idx / (NV * Sm1);
        int rem = idx - i * (NV * Sm1);
        int v = rem / Sm1;
        int k = rem - v * Sm1 + 1;
        int vx = v / 5 - 2, vy = v % 5 - 2;
        int pp = p0 + i;
        int hh = ((pp >> 5) + k * vy) & 31;
        int ww = ((pp & 31) + k * vx) & 31;
        int x = (hh << 5) + ww;
        const float* bp = &g_Bf[((size_t)(S - 1 - k) * HW + x) * 16];
        float s = 0.f;
#pragma unroll
        for (int n = 0; n < 16; n++) s += bp[n] * Cs[i][n];
        Gs[i][v][k] = s;
    }
    __syncthreads();

    float4 best = {-3e38f, -3e38f, -3e38f, -3e38f};
    if (g_uniA) {
        const float g0 = G0[pl];
#pragma unroll 1
        for (int g = 0; g < 5; g++) {
            float4 P[5], acc[5];
#pragma unroll
            for (int j = 0; j < 5; j++) {
                acc[j].x = f4o.x * g0; acc[j].y = f4o.y * g0;
                acc[j].z = f4o.z * g0; acc[j].w = f4o.w * g0;
                P[j] = e4o;
            }
#pragma unroll 1
            for (int k = 1; k < S; k++) {
#pragma unroll
                for (int j = 0; j < 5; j++) {
                    int v = g * 5 + j;
                    int vx = v / 5 - 2, vy = v % 5 - 2;
                    int hh = (h + k * vy) & 31;
                    int ww = (w + k * vx) & 31;
                    int x = (hh << 5) + ww;
                    const float4* ep = (const float4*)g_ef + (((size_t)(S - 1 - k) * HW + x) * 16 + dq) * 2;
                    float4 ee = ep[0];
                    float4 ff = ep[1];
                    float Gv = Gs[pl][v][k];
                    acc[j].x = fmaf(P[j].x * ff.x, Gv, acc[j].x);
                    acc[j].y = fmaf(P[j].y * ff.y, Gv, acc[j].y);
                    acc[j].z = fmaf(P[j].z * ff.z, Gv, acc[j].z);
                    acc[j].w = fmaf(P[j].w * ff.w, Gv, acc[j].w);
                    P[j].x *= ee.x; P[j].y *= ee.y; P[j].z *= ee.z; P[j].w *= ee.w;
                }
            }
#pragma unroll
            for (int j = 0; j < 5; j++) {
                best.x = fmaxf(best.x, acc[j].x);
                best.y = fmaxf(best.y, acc[j].y);
                best.z = fmaxf(best.z, acc[j].z);
                best.w = fmaxf(best.w, acc[j].w);
            }
        }
    } else {
        // generic A (correct for any A; slow fallback, not taken on this dataset)
#pragma unroll 1
        for (int v = 0; v < NV; v++) {
            int vx = v / 5 - 2, vy = v % 5 - 2;
            float4 accv = {0.f, 0.f, 0.f, 0.f};
#pragma unroll 1
            for (int n = 0; n < 16; n++) {
                float4 an4 = *(const float4*)&g_A[n * 64 + dq * 4];
                float4 rn4 = *(const float4*)&g_rA[n * 64 + dq * 4];
                float C = Cs[pl][n];
                float4 e0;
                e0.x = __expf(dl4.x * an4.x); e0.y = __expf(dl4.y * an4.y);
                e0.z = __expf(dl4.z * an4.z); e0.w = __expf(dl4.w * an4.w);
                float bc = Bs[pl][n] * C;
                float4 P = e0, a4c;
                a4c.x = (e0.x - 1.f) * rn4.x * u4.x * bc;
                a4c.y = (e0.y - 1.f) * rn4.y * u4.y * bc;
                a4c.z = (e0.z - 1.f) * rn4.z * u4.z * bc;
                a4c.w = (e0.w - 1.f) * rn4.w * u4.w * bc;
                for (int k = 1; k < S; k++) {
                    int hh = (h + k * vy) & 31;
                    int ww = (w + k * vx) & 31;
                    int x = (hh << 5) + ww;
                    int sl = S - 1 - k;
                    float4 dl = *(const float4*)&g_dl[((size_t)sl * HW + x) * 64 + dq * 4];
                    float4 uu = *(const float4*)&g_uf[((size_t)sl * HW + x) * 64 + dq * 4];
                    float Bt = g_Bf[((size_t)sl * HW + x) * 16 + n] * C;
                    float4 ee;
                    ee.x = __expf(dl.x * an4.x); ee.y = __expf(dl.y * an4.y);
                    ee.z = __expf(dl.z * an4.z); ee.w = __expf(dl.w * an4.w);
                    a4c.x = fmaf(P.x * (ee.x - 1.f) * rn4.x * uu.x, Bt, a4c.x);
                    a4c.y = fmaf(P.y * (ee.y - 1.f) * rn4.y * uu.y, Bt, a4c.y);
                    a4c.z = fmaf(P.z * (ee.z - 1.f) * rn4.z * uu.z, Bt, a4c.z);
                    a4c.w = fmaf(P.w * (ee.w - 1.f) * rn4.w * uu.w, Bt, a4c.w);
                    P.x *= ee.x; P.y *= ee.y; P.z *= ee.z; P.w *= ee.w;
                }
                accv.x += a4c.x; accv.y += a4c.y; accv.z += a4c.z; accv.w += a4c.w;
            }
            best.x = fmaxf(best.x, accv.x);
            best.y = fmaxf(best.y, accv.y);
            best.z = fmaxf(best.z, accv.z);
            best.w = fmaxf(best.w, accv.w);
        }
    }

    float4 dk = *(const float4*)&Dskip[dq * 4];
    float4 o;
    o.x = fmaf(dk.x, u4.x, best.x);
    o.y = fmaf(dk.y, u4.y, best.y);
    o.z = fmaf(dk.z, u4.z, best.z);
    o.w = fmaf(dk.w, u4.w, best.w);
    *(float4*)&ymax[p * 64 + dq * 4] = o;
}

// ---------------- launch ----------------
extern "C" void kernel_launch(void* const* d_in, const int* in_sizes, int n_in,
                              void* d_out, int out_size)
{
    const float* input_seq = (const float*)d_in[0];
    const float* enc_w1 = (const float*)d_in[1];
    const float* enc_b1 = (const float*)d_in[2];
    const float* enc_w2 = (const float*)d_in[3];
    const float* enc_b2 = (const float*)d_in[4];
    const float* wd     = (const float*)d_in[5];
    const float* bd     = (const float*)d_in[6];
    const float* wB     = (const float*)d_in[7];
    const float* wC     = (const float*)d_in[8];
    const float* logA   = (const float*)d_in[9];
    const float* Dskip  = (const float*)d_in[10];
    const float* dt_inv = (const float*)d_in[11];
    const float* dec_w1 = (const float*)d_in[12];
    const float* dec_b1 = (const float*)d_in[13];
    const float* dec_w2 = (const float*)d_in[14];
    const float* dec_b2 = (const float*)d_in[15];
    const float* dec_w3 = (const float*)d_in[16];
    const float* dec_b3 = (const float*)d_in[17];
    float* out = (float*)d_out;

    float *p_u, *p_e1, *p_cc, *p_wpack, *p_bpack, *p_ymax, *p_d1, *p_d2;
    cudaGetSymbolAddress((void**)&p_u, g_u);
    cudaGetSymbolAddress((void**)&p_e1, g_e1);
    cudaGetSymbolAddress((void**)&p_cc, g_cc);
    cudaGetSymbolAddress((void**)&p_wpack, g_wpack);
    cudaGetSymbolAddress((void**)&p_bpack, g_bpack);
    cudaGetSymbolAddress((void**)&p_ymax, g_ymax);
    cudaGetSymbolAddress((void**)&p_d1, g_d1);
    cudaGetSymbolAddress((void**)&p_d2, g_d2);

    pack_w<<<216, 256>>>(wd, bd, wB, wC, logA);
    check_uni<<<1, 256>>>(logA);

    // ---- encode: batched over 4 frames; no SSM state, just history fields ----
    conv1_cl<<<dim3(8, 16, TIN), 128>>>(input_seq, enc_w1, enc_b1, p_e1);
    conv_cl<true><<<dim3(32, 16, TIN), 64>>>(p_e1, enc_w2, enc_b2, p_u, DM);
    conv_cl<false><<<dim3(32, 24, TIN), 64>>>(p_u, p_wpack, p_bpack, p_cc, 96);
    prep<<<dim3(128, 1, TIN), 128>>>(p_cc, p_u, dt_inv);

    // ---- decode ----
    int steps = out_size / HW;
    for (int t = 0; t < steps; t++) {
        const float* src = (t == 0) ? (input_seq + 3 * HW) : (out + (size_t)(t - 1) * HW);
        conv1_cl<<<dim3(8, 16, 1), 128>>>(src, enc_w1, enc_b1, p_e1);
        conv_cl<true><<<dim3(32, 16, 1), 64>>>(p_e1, enc_w2, enc_b2, p_u, DM);
        conv_cl<false><<<dim3(32, 24, 1), 64>>>(p_u, p_wpack, p_bpack, p_cc, 96);
        fused_y<<<128, 128>>>(p_cc, p_u, Dskip, dt_inv, TIN + 1 + t, p_ymax);
        conv_cl<true><<<dim3(32, 16, 1), 64>>>(p_ymax, dec_w1, dec_b1, p_d1, DM);
        conv_cl<true><<<dim3(32, 16, 1), 64>>>(p_d1, dec_w2, dec_b2, p_d2, DM);
        conv_out<<<32, 128>>>(p_d2, dec_w3, dec_b3, out + (size_t)t * HW);
    }
}